// round 12
// baseline (speedup 1.0000x reference)
#include <cuda_runtime.h>
#include <math.h>

// SSMLayerFFTComplex: diagonal complex SSM (conjugate pairs) via exact linear
// recurrence instead of FFT convolution.
//
//   lam = -softplus(raw_lambda) + i*raw_omega          (per pair p)
//   A_d = exp(lam), factor = (A_d-1)/lam  (ZOH, DT=1)
//   w[b,p,t] = sum_i B_c[i,p] * u[b,i,t]               (real)
//   x[t]     = A_d * x[t-1] + factor * w[t]            (complex scan)
//   y[b,o,t] = sum_p C[p,o] * 2*Re(x[b,p,t])           (real GEMM)
//
// R11 post-mortem: split won; K2 (23.1us) is latency-exposed (issue 26.7%)
// and grid-capped at 512 blocks. R12: K2 CHUNK 64->32 => 1024 blocks, one
// wave at ~7 blocks/SM (occ ~43%, 2x warps for latency hiding) at the cost
// of +33% scan redundancy (warm-up 32/64). K1 unchanged.

namespace {
constexpr int T_TOT  = 4096;
constexpr int IN_CH  = 32;
constexpr int OUT_CH = 32;
constexpr int NP     = 128;
constexpr int WARM   = 32;             // warm-up timesteps (K2)

// K1 tile: block = 128 threads computes [64 t][NP p]; thread = 8p x 8t.
constexpr int K1_CHUNK = 64;
constexpr int K1_U_FL  = IN_CH * K1_CHUNK;   // 2048
constexpr int K1_BC_FL = IN_CH * NP;         // 4096
constexpr int SMEM1_BYTES = (K1_U_FL + K1_BC_FL) * (int)sizeof(float);  // 24,576 B

// K2: CHUNK=32 useful timesteps, 32 warm-up.
constexpr int CHUNK  = 32;
constexpr int LW     = CHUNK + WARM;   // 64
constexpr int GST    = 34;             // g row stride (b64-aligned, 2-way STS only)
constexpr int G_FL   = NP * GST;       // 4352
constexpr int SMEM2_BYTES = G_FL * (int)sizeof(float);  // 17,408 B

constexpr int MAXB = 8;
}

__device__ float w_buf[MAXB * T_TOT * NP];   // scratch: w[b][t][p]

typedef unsigned long long u64;

__device__ __forceinline__ u64 ffma2(u64 a, u64 b, u64 c) {
    u64 d;
    asm("fma.rn.f32x2 %0, %1, %2, %3;" : "=l"(d) : "l"(a), "l"(b), "l"(c));
    return d;
}
__device__ __forceinline__ u64 pack2(float lo, float hi) {
    u64 d;
    asm("mov.b64 %0, {%1, %2};" : "=l"(d) : "f"(lo), "f"(hi));
    return d;
}
__device__ __forceinline__ void unpack2(u64 v, float& lo, float& hi) {
    asm("mov.b64 {%0, %1}, %2;" : "=f"(lo), "=f"(hi) : "l"(v));
}

// ---------------------------------------------------------------------------
// Kernel 1: w[b][t][p] = sum_i Bc[i][p] * u[b][i][t]   (register-tiled GEMM)
// ---------------------------------------------------------------------------
__global__ __launch_bounds__(128, 4)
void ssm_wmix_kernel(const float* __restrict__ u,
                     const float* __restrict__ Bc)
{
    extern __shared__ float smem[];
    float* u_s  = smem;                 // [IN_CH][K1_CHUNK]
    float* bc_s = smem + K1_U_FL;       // [IN_CH][NP]

    const int tid = threadIdx.x;
    const int ct  = blockIdx.x;
    const int b   = blockIdx.y;
    const int t0  = ct * K1_CHUNK;

    const float* ug = u + (size_t)b * IN_CH * T_TOT + t0;
    for (int idx = tid; idx < K1_U_FL; idx += 128) {
        int i = idx >> 6;           // / K1_CHUNK
        int j = idx & 63;
        u_s[idx] = ug[i * T_TOT + j];
    }
    for (int idx = tid; idx < K1_BC_FL; idx += 128) bc_s[idx] = Bc[idx];
    __syncthreads();

    const int pq = tid & 15;        // p block: [8*pq, 8*pq+8)
    const int tq = tid >> 4;        // t block: [8*tq, 8*tq+8)

    u64 acc[8][4];                  // [t][p-pair]
#pragma unroll
    for (int t = 0; t < 8; ++t)
#pragma unroll
        for (int q = 0; q < 4; ++q) acc[t][q] = 0ull;

    const float* bcb = bc_s + 8 * pq;
    const float* ub  = u_s + 8 * tq;
#pragma unroll 4
    for (int k = 0; k < IN_CH; ++k) {
        ulonglong2 bcp = *reinterpret_cast<const ulonglong2*>(bcb + k * NP);
        ulonglong2 bcq = *reinterpret_cast<const ulonglong2*>(bcb + k * NP + 4);
        float4 ua  = *reinterpret_cast<const float4*>(ub + k * K1_CHUNK);
        float4 ub4 = *reinterpret_cast<const float4*>(ub + k * K1_CHUNK + 4);
        u64 td[8];
        td[0] = pack2(ua.x, ua.x);   td[1] = pack2(ua.y, ua.y);
        td[2] = pack2(ua.z, ua.z);   td[3] = pack2(ua.w, ua.w);
        td[4] = pack2(ub4.x, ub4.x); td[5] = pack2(ub4.y, ub4.y);
        td[6] = pack2(ub4.z, ub4.z); td[7] = pack2(ub4.w, ub4.w);
        u64 bp[4] = {bcp.x, bcp.y, bcq.x, bcq.y};
#pragma unroll
        for (int t = 0; t < 8; ++t)
#pragma unroll
            for (int q = 0; q < 4; ++q)
                acc[t][q] = ffma2(bp[q], td[t], acc[t][q]);
    }

    float* wb = w_buf + ((size_t)b * T_TOT + t0 + 8 * tq) * NP + 8 * pq;
#pragma unroll
    for (int t = 0; t < 8; ++t) {
        ulonglong2 v0; v0.x = acc[t][0]; v0.y = acc[t][1];
        ulonglong2 v1; v1.x = acc[t][2]; v1.y = acc[t][3];
        *reinterpret_cast<ulonglong2*>(wb + t * NP)     = v0;
        *reinterpret_cast<ulonglong2*>(wb + t * NP + 4) = v1;
    }
}

// ---------------------------------------------------------------------------
// Kernel 2: scan + output GEMM  (CHUNK=32 -> 1024 blocks, ~7/SM)
// ---------------------------------------------------------------------------
__global__ __launch_bounds__(128, 7)
void ssm_scan_kernel(const float* __restrict__ raw_lambda,
                     const float* __restrict__ raw_omega,
                     const float* __restrict__ Cp,   // [NP][OUT_CH]
                     float* __restrict__ y)          // [B][OUT_CH][T]
{
    extern __shared__ float smem[];
    float* g_s = smem;              // [NP][GST]  (32-t chunk)

    const int tid   = threadIdx.x;
    const int wp    = tid >> 5;
    const int lane  = tid & 31;
    const int chunk = blockIdx.x;
    const int b     = blockIdx.y;
    const int t0    = chunk * CHUNK;

    // ---- per-pair parameters (thread = pair p) ----
    const int p = tid;
    float rl = raw_lambda[p];
    float li = raw_omega[p];
    float lr = -log1pf(expf(rl));            // -softplus
    float er = expf(lr);
    float ar = er * cosf(li);                // A_d
    float ai = er * sinf(li);
    float nr = ar - 1.0f, ni = ai;
    float den = lr * lr + li * li;
    float fr, fi;
    if (den > 1e-12f) {
        float inv = 1.0f / den;
        fr = (nr * lr + ni * li) * inv;      // (A_d-1)/lam
        fi = (ni * lr - nr * li) * inv;
    } else {
        fr = 1.0f; fi = 0.0f;                // DT = 1
    }
    fr *= 2.0f; fi *= 2.0f;                  // fold 2*Re(conjugate pair)

    // ---- stage B: scan over [t0-WARM, t0+CHUNK), w from L2 scratch ----
    const float* wrow = w_buf + (size_t)b * T_TOT * NP + p;
    float xr = 0.0f, xi = 0.0f;
#pragma unroll 1
    for (int jb = 0; jb < LW; jb += 8) {
        const int tb = t0 - WARM + jb;
        float wv[8];
        if (tb >= 0) {                       // uniform per block
#pragma unroll
            for (int k = 0; k < 8; ++k) wv[k] = wrow[(size_t)(tb + k) * NP];
        } else {                             // WARM%8==0 -> whole group < 0
#pragma unroll
            for (int k = 0; k < 8; ++k) wv[k] = 0.0f;
        }

        float xrs[8];
#pragma unroll
        for (int k = 0; k < 8; ++k) {
            float nxr = fmaf(ar, xr, fmaf(-ai, xi, fr * wv[k]));
            float nxi = fmaf(ar, xi, fmaf( ai, xr, fi * wv[k]));
            xr = nxr; xi = nxi;
            xrs[k] = xr;                      // already x2 via factor
        }
        if (jb >= WARM) {
            float* gr = &g_s[p * GST + (jb - WARM)];
            *reinterpret_cast<u64*>(gr + 0) = pack2(xrs[0], xrs[1]);
            *reinterpret_cast<u64*>(gr + 2) = pack2(xrs[2], xrs[3]);
            *reinterpret_cast<u64*>(gr + 4) = pack2(xrs[4], xrs[5]);
            *reinterpret_cast<u64*>(gr + 6) = pack2(xrs[6], xrs[7]);
        }
    }

    __syncthreads();

    // ---- stage C: y[o, t] = sum_p C[p,o] * g[p,t], thread = 8ch x 1t ----
    // C read via coalesced LDG.128 (16KB, shared by all blocks, L1-hot).
    const int oct = lane & 3;                // channel octet
    const int tl  = wp * 8 + (lane >> 2);    // local t 0..31

    u64 a01 = 0ull, a23 = 0ull, a45 = 0ull, a67 = 0ull;
    const float* cb = Cp + oct * 8;
#pragma unroll 4
    for (int pp = 0; pp < NP; ++pp) {
        ulonglong2 cA = *reinterpret_cast<const ulonglong2*>(cb + pp * OUT_CH);
        ulonglong2 cB = *reinterpret_cast<const ulonglong2*>(cb + pp * OUT_CH + 4);
        float g = g_s[pp * GST + tl];
        u64 gg = pack2(g, g);
        a01 = ffma2(cA.x, gg, a01);
        a23 = ffma2(cA.y, gg, a23);
        a45 = ffma2(cB.x, gg, a45);
        a67 = ffma2(cB.y, gg, a67);
    }

    const int tg = t0 + tl;
    float* yb = y + ((size_t)b * OUT_CH + oct * 8) * T_TOT + tg;
    float c0, c1;
    unpack2(a01, c0, c1);
    yb[0 * T_TOT] = c0;  yb[1 * T_TOT] = c1;
    unpack2(a23, c0, c1);
    yb[2 * T_TOT] = c0;  yb[3 * T_TOT] = c1;
    unpack2(a45, c0, c1);
    yb[4 * T_TOT] = c0;  yb[5 * T_TOT] = c1;
    unpack2(a67, c0, c1);
    yb[6 * T_TOT] = c0;  yb[7 * T_TOT] = c1;
}

extern "C" void kernel_launch(void* const* d_in, const int* in_sizes, int n_in,
                              void* d_out, int out_size)
{
    const float* u   = (const float*)d_in[0];
    const float* rlb = (const float*)d_in[1];
    const float* rom = (const float*)d_in[2];
    const float* Bc  = (const float*)d_in[3];
    const float* Cp  = (const float*)d_in[4];
    float* y = (float*)d_out;

    const int B = in_sizes[0] / (IN_CH * T_TOT);  // 8

    cudaFuncSetAttribute(ssm_wmix_kernel,
                         cudaFuncAttributeMaxDynamicSharedMemorySize, SMEM1_BYTES);
    cudaFuncSetAttribute(ssm_scan_kernel,
                         cudaFuncAttributeMaxDynamicSharedMemorySize, SMEM2_BYTES);

    dim3 grid1(T_TOT / K1_CHUNK, B);   // 64 x 8 = 512 blocks
    ssm_wmix_kernel<<<grid1, 128, SMEM1_BYTES>>>(u, Bc);

    dim3 grid2(T_TOT / CHUNK, B);      // 128 x 8 = 1024 blocks, one wave at 7/SM
    ssm_scan_kernel<<<grid2, 128, SMEM2_BYTES>>>(rlb, rom, Cp, y);
}

// round 13
// speedup vs baseline: 1.1774x; 1.1774x over previous
#include <cuda_runtime.h>
#include <math.h>

// SSMLayerFFTComplex: diagonal complex SSM (conjugate pairs) via exact linear
// recurrence instead of FFT convolution.
//
//   lam = -softplus(raw_lambda) + i*raw_omega          (per pair p)
//   A_d = exp(lam), factor = (A_d-1)/lam  (ZOH, DT=1)
//   w[b,p,t] = sum_i B_c[i,p] * u[b,i,t]               (real)
//   x[t]     = A_d * x[t-1] + factor * w[t]            (complex scan)
//   y[b,o,t] = sum_p C[p,o] * 2*Re(x[b,p,t])           (real GEMM)
//
// R12 post-mortem: CHUNK=32 doubled C-load cost/output + 33% scan redundancy;
// occupancy gain couldn't pay for the work. R13 = R11 skeleton (best) with:
//   K1: u staged PRE-DUPLICATED as (v,v) u64 -> pack-free FFMA2 GEMM loop.
//   K2: scan double-buffers w groups (prefetch next 8 LDGs before the scan
//       chain of the current 8), alternating register buffers.
//   K2 stage C: unroll 8. Structure otherwise identical to R11.

namespace {
constexpr int T_TOT  = 4096;
constexpr int IN_CH  = 32;
constexpr int OUT_CH = 32;
constexpr int NP     = 128;
constexpr int WARM   = 32;             // warm-up timesteps (K2)

// K1 tile: block = 128 threads computes [64 t][NP p]; thread = 8p x 8t.
constexpr int K1_CHUNK = 64;
constexpr int K1_U2_BYTES = IN_CH * K1_CHUNK * 8;   // dup u64: 16,384 B
constexpr int K1_BC_FL    = IN_CH * NP;             // 4096 floats
constexpr int SMEM1_BYTES = K1_U2_BYTES + K1_BC_FL * (int)sizeof(float); // 32,768 B

// K2: CHUNK=64 useful timesteps, 32 warm-up (R11 config).
constexpr int CHUNK  = 64;
constexpr int LW     = CHUNK + WARM;   // 96
constexpr int GST    = 66;             // g row stride (b64-aligned, 2-way STS only)
constexpr int G_FL   = NP * GST;       // 8448
constexpr int SMEM2_BYTES = G_FL * (int)sizeof(float);  // 33,792 B

constexpr int MAXB = 8;
}

__device__ float w_buf[MAXB * T_TOT * NP];   // scratch: w[b][t][p]

typedef unsigned long long u64;

__device__ __forceinline__ u64 ffma2(u64 a, u64 b, u64 c) {
    u64 d;
    asm("fma.rn.f32x2 %0, %1, %2, %3;" : "=l"(d) : "l"(a), "l"(b), "l"(c));
    return d;
}
__device__ __forceinline__ u64 pack2(float lo, float hi) {
    u64 d;
    asm("mov.b64 %0, {%1, %2};" : "=l"(d) : "f"(lo), "f"(hi));
    return d;
}
__device__ __forceinline__ void unpack2(u64 v, float& lo, float& hi) {
    asm("mov.b64 {%0, %1}, %2;" : "=f"(lo), "=f"(hi) : "l"(v));
}

// ---------------------------------------------------------------------------
// Kernel 1: w[b][t][p] = sum_i Bc[i][p] * u[b][i][t]   (register-tiled GEMM)
// u staged pre-duplicated: u_s2[i][t] = (u,u) as u64 -> no packs in the loop.
// ---------------------------------------------------------------------------
__global__ __launch_bounds__(128, 4)
void ssm_wmix_kernel(const float* __restrict__ u,
                     const float* __restrict__ Bc)
{
    extern __shared__ char smem1[];
    u64*   u_s2 = reinterpret_cast<u64*>(smem1);            // [IN_CH][K1_CHUNK] dup pairs
    float* bc_s = reinterpret_cast<float*>(smem1 + K1_U2_BYTES);  // [IN_CH][NP]

    const int tid = threadIdx.x;
    const int ct  = blockIdx.x;
    const int b   = blockIdx.y;
    const int t0  = ct * K1_CHUNK;

    const float* ug = u + (size_t)b * IN_CH * T_TOT + t0;
    for (int idx = tid; idx < IN_CH * K1_CHUNK; idx += 128) {
        int i = idx >> 6;           // / K1_CHUNK
        int j = idx & 63;
        float v = ug[i * T_TOT + j];
        u_s2[idx] = pack2(v, v);    // duplicated pair
    }
    for (int idx = tid; idx < K1_BC_FL; idx += 128) bc_s[idx] = Bc[idx];
    __syncthreads();

    const int pq = tid & 15;        // p block: [8*pq, 8*pq+8)
    const int tq = tid >> 4;        // t block: [8*tq, 8*tq+8)

    u64 acc[8][4];                  // [t][p-pair]
#pragma unroll
    for (int t = 0; t < 8; ++t)
#pragma unroll
        for (int q = 0; q < 4; ++q) acc[t][q] = 0ull;

    const float* bcb = bc_s + 8 * pq;
    const u64*   ub2 = u_s2 + 8 * tq;
#pragma unroll 4
    for (int k = 0; k < IN_CH; ++k) {
        ulonglong2 t01 = *reinterpret_cast<const ulonglong2*>(ub2 + (size_t)k * K1_CHUNK + 0);
        ulonglong2 t23 = *reinterpret_cast<const ulonglong2*>(ub2 + (size_t)k * K1_CHUNK + 2);
        ulonglong2 t45 = *reinterpret_cast<const ulonglong2*>(ub2 + (size_t)k * K1_CHUNK + 4);
        ulonglong2 t67 = *reinterpret_cast<const ulonglong2*>(ub2 + (size_t)k * K1_CHUNK + 6);
        ulonglong2 bcp = *reinterpret_cast<const ulonglong2*>(bcb + k * NP);
        ulonglong2 bcq = *reinterpret_cast<const ulonglong2*>(bcb + k * NP + 4);
        u64 td[8] = {t01.x, t01.y, t23.x, t23.y, t45.x, t45.y, t67.x, t67.y};
        u64 bp[4] = {bcp.x, bcp.y, bcq.x, bcq.y};
#pragma unroll
        for (int t = 0; t < 8; ++t)
#pragma unroll
            for (int q = 0; q < 4; ++q)
                acc[t][q] = ffma2(bp[q], td[t], acc[t][q]);
    }

    float* wb = w_buf + ((size_t)b * T_TOT + t0 + 8 * tq) * NP + 8 * pq;
#pragma unroll
    for (int t = 0; t < 8; ++t) {
        ulonglong2 v0; v0.x = acc[t][0]; v0.y = acc[t][1];
        ulonglong2 v1; v1.x = acc[t][2]; v1.y = acc[t][3];
        *reinterpret_cast<ulonglong2*>(wb + t * NP)     = v0;
        *reinterpret_cast<ulonglong2*>(wb + t * NP + 4) = v1;
    }
}

// ---------------------------------------------------------------------------
// Kernel 2: scan (with w-group prefetch) + output GEMM
// ---------------------------------------------------------------------------
__global__ __launch_bounds__(128, 4)
void ssm_scan_kernel(const float* __restrict__ raw_lambda,
                     const float* __restrict__ raw_omega,
                     const float* __restrict__ Cp,   // [NP][OUT_CH]
                     float* __restrict__ y)          // [B][OUT_CH][T]
{
    extern __shared__ float smem[];
    float* g_s = smem;              // [NP][GST]  (full 64-t chunk)

    const int tid   = threadIdx.x;
    const int wp    = tid >> 5;
    const int lane  = tid & 31;
    const int chunk = blockIdx.x;
    const int b     = blockIdx.y;
    const int t0    = chunk * CHUNK;

    // ---- per-pair parameters (thread = pair p) ----
    const int p = tid;
    float rl = raw_lambda[p];
    float li = raw_omega[p];
    float lr = -log1pf(expf(rl));            // -softplus
    float er = expf(lr);
    float ar = er * cosf(li);                // A_d
    float ai = er * sinf(li);
    float nr = ar - 1.0f, ni = ai;
    float den = lr * lr + li * li;
    float fr, fi;
    if (den > 1e-12f) {
        float inv = 1.0f / den;
        fr = (nr * lr + ni * li) * inv;      // (A_d-1)/lam
        fi = (ni * lr - nr * li) * inv;
    } else {
        fr = 1.0f; fi = 0.0f;                // DT = 1
    }
    fr *= 2.0f; fi *= 2.0f;                  // fold 2*Re(conjugate pair)

    // ---- stage B: scan over [t0-WARM, t0+CHUNK) with group prefetch ----
    const float* wrow = w_buf + (size_t)b * T_TOT * NP + p;
    float xr = 0.0f, xi = 0.0f;
    float wa[8], wb8[8];

    // load group helper (uniform branch; WARM%8==0 -> group wholly <0 or >=0)
#define LOADGRP(JB, DST)                                              \
    {   const int tb_ = t0 - WARM + (JB);                             \
        if (tb_ >= 0) {                                               \
            _Pragma("unroll")                                         \
            for (int k_ = 0; k_ < 8; ++k_)                            \
                (DST)[k_] = wrow[(size_t)(tb_ + k_) * NP];            \
        } else {                                                      \
            _Pragma("unroll")                                         \
            for (int k_ = 0; k_ < 8; ++k_) (DST)[k_] = 0.0f;          \
        }                                                             \
    }

#define SCANGRP(JB, SRC)                                              \
    {   float xrs_[8];                                                \
        _Pragma("unroll")                                             \
        for (int k_ = 0; k_ < 8; ++k_) {                              \
            float nxr_ = fmaf(ar, xr, fmaf(-ai, xi, fr * (SRC)[k_])); \
            float nxi_ = fmaf(ar, xi, fmaf( ai, xr, fi * (SRC)[k_])); \
            xr = nxr_; xi = nxi_;                                     \
            xrs_[k_] = xr;                                            \
        }                                                             \
        if ((JB) >= WARM) {                                           \
            float* gr_ = &g_s[p * GST + ((JB) - WARM)];               \
            *reinterpret_cast<u64*>(gr_ + 0) = pack2(xrs_[0], xrs_[1]); \
            *reinterpret_cast<u64*>(gr_ + 2) = pack2(xrs_[2], xrs_[3]); \
            *reinterpret_cast<u64*>(gr_ + 4) = pack2(xrs_[4], xrs_[5]); \
            *reinterpret_cast<u64*>(gr_ + 6) = pack2(xrs_[6], xrs_[7]); \
        }                                                             \
    }

    LOADGRP(0, wa);
#pragma unroll 1
    for (int jb = 0; jb < LW; jb += 16) {
        LOADGRP(jb + 8, wb8);        // prefetch while wa's chain runs
        SCANGRP(jb, wa);
        if (jb + 16 < LW) LOADGRP(jb + 16, wa);
        SCANGRP(jb + 8, wb8);
    }
#undef LOADGRP
#undef SCANGRP

    __syncthreads();

    // ---- stage C: y[o, t] = sum_p C[p,o] * g[p,t], thread = 8ch x 2t ----
    // C read via coalesced LDG.128 (16KB, shared by all blocks, L1-hot).
    const int oct = lane & 3;                       // channel octet
    const int tl  = wp * 16 + (lane >> 2) * 2;      // local t (even), 0..62

    u64 a01t0 = 0ull, a23t0 = 0ull, a45t0 = 0ull, a67t0 = 0ull;
    u64 a01t1 = 0ull, a23t1 = 0ull, a45t1 = 0ull, a67t1 = 0ull;

    const float* cb = Cp + oct * 8;
#pragma unroll 8
    for (int pp = 0; pp < NP; ++pp) {
        ulonglong2 cA = *reinterpret_cast<const ulonglong2*>(cb + pp * OUT_CH);
        ulonglong2 cB = *reinterpret_cast<const ulonglong2*>(cb + pp * OUT_CH + 4);
        u64 gp = *reinterpret_cast<const u64*>(&g_s[pp * GST + tl]);
        float g0, g1;
        unpack2(gp, g0, g1);
        u64 gg0 = pack2(g0, g0);
        u64 gg1 = pack2(g1, g1);
        a01t0 = ffma2(cA.x, gg0, a01t0);
        a23t0 = ffma2(cA.y, gg0, a23t0);
        a45t0 = ffma2(cB.x, gg0, a45t0);
        a67t0 = ffma2(cB.y, gg0, a67t0);
        a01t1 = ffma2(cA.x, gg1, a01t1);
        a23t1 = ffma2(cA.y, gg1, a23t1);
        a45t1 = ffma2(cB.x, gg1, a45t1);
        a67t1 = ffma2(cB.y, gg1, a67t1);
    }

    const int tg = t0 + tl;
    float* yb = y + ((size_t)b * OUT_CH + oct * 8) * T_TOT + tg;
    float c0t0, c1t0, c0t1, c1t1;
    unpack2(a01t0, c0t0, c1t0); unpack2(a01t1, c0t1, c1t1);
    *reinterpret_cast<float2*>(yb + 0 * T_TOT) = make_float2(c0t0, c0t1);
    *reinterpret_cast<float2*>(yb + 1 * T_TOT) = make_float2(c1t0, c1t1);
    unpack2(a23t0, c0t0, c1t0); unpack2(a23t1, c0t1, c1t1);
    *reinterpret_cast<float2*>(yb + 2 * T_TOT) = make_float2(c0t0, c0t1);
    *reinterpret_cast<float2*>(yb + 3 * T_TOT) = make_float2(c1t0, c1t1);
    unpack2(a45t0, c0t0, c1t0); unpack2(a45t1, c0t1, c1t1);
    *reinterpret_cast<float2*>(yb + 4 * T_TOT) = make_float2(c0t0, c0t1);
    *reinterpret_cast<float2*>(yb + 5 * T_TOT) = make_float2(c1t0, c1t1);
    unpack2(a67t0, c0t0, c1t0); unpack2(a67t1, c0t1, c1t1);
    *reinterpret_cast<float2*>(yb + 6 * T_TOT) = make_float2(c0t0, c0t1);
    *reinterpret_cast<float2*>(yb + 7 * T_TOT) = make_float2(c1t0, c1t1);
}

extern "C" void kernel_launch(void* const* d_in, const int* in_sizes, int n_in,
                              void* d_out, int out_size)
{
    const float* u   = (const float*)d_in[0];
    const float* rlb = (const float*)d_in[1];
    const float* rom = (const float*)d_in[2];
    const float* Bc  = (const float*)d_in[3];
    const float* Cp  = (const float*)d_in[4];
    float* y = (float*)d_out;

    const int B = in_sizes[0] / (IN_CH * T_TOT);  // 8

    cudaFuncSetAttribute(ssm_wmix_kernel,
                         cudaFuncAttributeMaxDynamicSharedMemorySize, SMEM1_BYTES);
    cudaFuncSetAttribute(ssm_scan_kernel,
                         cudaFuncAttributeMaxDynamicSharedMemorySize, SMEM2_BYTES);

    dim3 grid1(T_TOT / K1_CHUNK, B);   // 64 x 8 = 512 blocks
    ssm_wmix_kernel<<<grid1, 128, SMEM1_BYTES>>>(u, Bc);

    dim3 grid2(T_TOT / CHUNK, B);      // 64 x 8 = 512 blocks, one wave at 4/SM
    ssm_scan_kernel<<<grid2, 128, SMEM2_BYTES>>>(rlb, rom, Cp, y);
}

// round 14
// speedup vs baseline: 1.1785x; 1.0009x over previous
#include <cuda_runtime.h>
#include <math.h>

// SSMLayerFFTComplex: diagonal complex SSM (conjugate pairs) via exact linear
// recurrence instead of FFT convolution.
//
//   lam = -softplus(raw_lambda) + i*raw_omega          (per pair p)
//   A_d = exp(lam), factor = (A_d-1)/lam  (ZOH, DT=1)
//   w[b,p,t] = sum_i B_c[i,p] * u[b,i,t]               (real)
//   x[t]     = A_d * x[t-1] + factor * w[t]            (complex scan)
//   y[b,o,t] = sum_p C[p,o] * 2*Re(x[b,p,t])           (real GEMM)
//
// R13 post-mortem: K2 down to 21.2us but wall flat at 34.8 -> K1 (~12us) +
// serialization is the wall. R14: ONE launch, 1024 blocks. bids 0-511 = K1
// role (w GEMM, verbatim R13), bids 512-1023 = K2 role (scan + out GEMM,
// verbatim R13). Per-(b,ct) ready-flags: producer syncthreads+threadfence+
// atomicExch; consumer spins (nanosleep backoff) on its <=2 producer flags.
// Wave 1 (4 blocks/SM = 592) contains ALL producers -> deadlock-free; K2
// blocks start as soon as their two producers finish (~3us) instead of 13us.
// Flags zeroed per launch via cudaMemsetAsync (graph-capturable).

namespace {
constexpr int T_TOT  = 4096;
constexpr int IN_CH  = 32;
constexpr int OUT_CH = 32;
constexpr int NP     = 128;
constexpr int WARM   = 32;

constexpr int K1_CHUNK = 64;
constexpr int K1_U2_BYTES = IN_CH * K1_CHUNK * 8;     // dup u64: 16,384 B
constexpr int K1_BC_FL    = IN_CH * NP;               // 4096 floats

constexpr int CHUNK  = 64;
constexpr int LW     = CHUNK + WARM;   // 96
constexpr int GST    = 66;             // g row stride (b64-aligned)
constexpr int G_FL   = NP * GST;       // 8448 floats = 33,792 B

constexpr int SMEM_BYTES = G_FL * (int)sizeof(float); // 33,792 (covers K1's 32,768)

constexpr int MAXB   = 8;
constexpr int NCHUNK = T_TOT / K1_CHUNK;   // 64
constexpr int NBLK1  = NCHUNK * MAXB;      // 512
}

__device__ float w_buf[MAXB * T_TOT * NP];       // scratch: w[b][t][p]
__device__ unsigned int w_flag[MAXB * NCHUNK];   // ready flags [b][ct]

typedef unsigned long long u64;

__device__ __forceinline__ u64 ffma2(u64 a, u64 b, u64 c) {
    u64 d;
    asm("fma.rn.f32x2 %0, %1, %2, %3;" : "=l"(d) : "l"(a), "l"(b), "l"(c));
    return d;
}
__device__ __forceinline__ u64 pack2(float lo, float hi) {
    u64 d;
    asm("mov.b64 %0, {%1, %2};" : "=l"(d) : "f"(lo), "f"(hi));
    return d;
}
__device__ __forceinline__ void unpack2(u64 v, float& lo, float& hi) {
    asm("mov.b64 {%0, %1}, %2;" : "=f"(lo), "=f"(hi) : "l"(v));
}

__global__ __launch_bounds__(128, 4)
void ssm_fused_kernel(const float* __restrict__ u,
                      const float* __restrict__ Bc,   // [IN_CH][NP]
                      const float* __restrict__ raw_lambda,
                      const float* __restrict__ raw_omega,
                      const float* __restrict__ Cp,   // [NP][OUT_CH]
                      float* __restrict__ y)          // [B][OUT_CH][T]
{
    extern __shared__ char smem_raw[];
    const int tid = threadIdx.x;
    const int bid = blockIdx.x;

    if (bid < NBLK1) {
        // ================= K1 role: w[b][t][p] = Bc^T u =================
        u64*   u_s2 = reinterpret_cast<u64*>(smem_raw);
        float* bc_s = reinterpret_cast<float*>(smem_raw + K1_U2_BYTES);

        const int ct = bid & (NCHUNK - 1);
        const int b  = bid >> 6;
        const int t0 = ct * K1_CHUNK;

        const float* ug = u + (size_t)b * IN_CH * T_TOT + t0;
        for (int idx = tid; idx < IN_CH * K1_CHUNK; idx += 128) {
            int i = idx >> 6;
            int j = idx & 63;
            float v = ug[i * T_TOT + j];
            u_s2[idx] = pack2(v, v);          // duplicated pair
        }
        for (int idx = tid; idx < K1_BC_FL; idx += 128) bc_s[idx] = Bc[idx];
        __syncthreads();

        const int pq = tid & 15;              // p block: [8*pq, 8*pq+8)
        const int tq = tid >> 4;              // t block: [8*tq, 8*tq+8)

        u64 acc[8][4];
#pragma unroll
        for (int t = 0; t < 8; ++t)
#pragma unroll
            for (int q = 0; q < 4; ++q) acc[t][q] = 0ull;

        const float* bcb = bc_s + 8 * pq;
        const u64*   ub2 = u_s2 + 8 * tq;
#pragma unroll 4
        for (int k = 0; k < IN_CH; ++k) {
            ulonglong2 t01 = *reinterpret_cast<const ulonglong2*>(ub2 + (size_t)k * K1_CHUNK + 0);
            ulonglong2 t23 = *reinterpret_cast<const ulonglong2*>(ub2 + (size_t)k * K1_CHUNK + 2);
            ulonglong2 t45 = *reinterpret_cast<const ulonglong2*>(ub2 + (size_t)k * K1_CHUNK + 4);
            ulonglong2 t67 = *reinterpret_cast<const ulonglong2*>(ub2 + (size_t)k * K1_CHUNK + 6);
            ulonglong2 bcp = *reinterpret_cast<const ulonglong2*>(bcb + k * NP);
            ulonglong2 bcq = *reinterpret_cast<const ulonglong2*>(bcb + k * NP + 4);
            u64 td[8] = {t01.x, t01.y, t23.x, t23.y, t45.x, t45.y, t67.x, t67.y};
            u64 bp[4] = {bcp.x, bcp.y, bcq.x, bcq.y};
#pragma unroll
            for (int t = 0; t < 8; ++t)
#pragma unroll
                for (int q = 0; q < 4; ++q)
                    acc[t][q] = ffma2(bp[q], td[t], acc[t][q]);
        }

        float* wb = w_buf + ((size_t)b * T_TOT + t0 + 8 * tq) * NP + 8 * pq;
#pragma unroll
        for (int t = 0; t < 8; ++t) {
            ulonglong2 v0; v0.x = acc[t][0]; v0.y = acc[t][1];
            ulonglong2 v1; v1.x = acc[t][2]; v1.y = acc[t][3];
            *reinterpret_cast<ulonglong2*>(wb + t * NP)     = v0;
            *reinterpret_cast<ulonglong2*>(wb + t * NP + 4) = v1;
        }

        // publish: all stores done -> fence -> flag
        __syncthreads();
        if (tid == 0) {
            __threadfence();
            atomicExch(&w_flag[(b << 6) + ct], 1u);
        }
        return;
    }

    // ================= K2 role: scan + output GEMM =================
    float* g_s = reinterpret_cast<float*>(smem_raw);   // [NP][GST]

    const int idx2  = bid - NBLK1;
    const int chunk = idx2 & (NCHUNK - 1);
    const int b     = idx2 >> 6;
    const int t0    = chunk * CHUNK;
    const int wp    = tid >> 5;
    const int lane  = tid & 31;

    // ---- per-pair parameters (independent of w; compute before waiting) ----
    const int p = tid;
    float rl = raw_lambda[p];
    float li = raw_omega[p];
    float lr = -log1pf(expf(rl));            // -softplus
    float er = expf(lr);
    float ar = er * cosf(li);                // A_d
    float ai = er * sinf(li);
    float nr = ar - 1.0f, ni = ai;
    float den = lr * lr + li * li;
    float fr, fi;
    if (den > 1e-12f) {
        float inv = 1.0f / den;
        fr = (nr * lr + ni * li) * inv;      // (A_d-1)/lam
        fi = (ni * lr - nr * li) * inv;
    } else {
        fr = 1.0f; fi = 0.0f;                // DT = 1
    }
    fr *= 2.0f; fi *= 2.0f;                  // fold 2*Re(conjugate pair)

    // ---- wait for producer chunks (b, chunk) and (b, chunk-1) ----
    if (tid == 0) {
        const int f0 = (b << 6) + chunk;
        while (atomicAdd(&w_flag[f0], 0u) == 0u) __nanosleep(64);
        if (chunk > 0)
            while (atomicAdd(&w_flag[f0 - 1], 0u) == 0u) __nanosleep(64);
        __threadfence();
    }
    __syncthreads();

    // ---- stage B: scan over [t0-WARM, t0+CHUNK) with group prefetch ----
    const float* wrow = w_buf + (size_t)b * T_TOT * NP + p;
    float xr = 0.0f, xi = 0.0f;
    float wa[8], wb8[8];

#define LOADGRP(JB, DST)                                              \
    {   const int tb_ = t0 - WARM + (JB);                             \
        if (tb_ >= 0) {                                               \
            _Pragma("unroll")                                         \
            for (int k_ = 0; k_ < 8; ++k_)                            \
                (DST)[k_] = wrow[(size_t)(tb_ + k_) * NP];            \
        } else {                                                      \
            _Pragma("unroll")                                         \
            for (int k_ = 0; k_ < 8; ++k_) (DST)[k_] = 0.0f;          \
        }                                                             \
    }

#define SCANGRP(JB, SRC)                                              \
    {   float xrs_[8];                                                \
        _Pragma("unroll")                                             \
        for (int k_ = 0; k_ < 8; ++k_) {                              \
            float nxr_ = fmaf(ar, xr, fmaf(-ai, xi, fr * (SRC)[k_])); \
            float nxi_ = fmaf(ar, xi, fmaf( ai, xr, fi * (SRC)[k_])); \
            xr = nxr_; xi = nxi_;                                     \
            xrs_[k_] = xr;                                            \
        }                                                             \
        if ((JB) >= WARM) {                                           \
            float* gr_ = &g_s[p * GST + ((JB) - WARM)];               \
            *reinterpret_cast<u64*>(gr_ + 0) = pack2(xrs_[0], xrs_[1]); \
            *reinterpret_cast<u64*>(gr_ + 2) = pack2(xrs_[2], xrs_[3]); \
            *reinterpret_cast<u64*>(gr_ + 4) = pack2(xrs_[4], xrs_[5]); \
            *reinterpret_cast<u64*>(gr_ + 6) = pack2(xrs_[6], xrs_[7]); \
        }                                                             \
    }

    LOADGRP(0, wa);
#pragma unroll 1
    for (int jb = 0; jb < LW; jb += 16) {
        LOADGRP(jb + 8, wb8);
        SCANGRP(jb, wa);
        if (jb + 16 < LW) LOADGRP(jb + 16, wa);
        SCANGRP(jb + 8, wb8);
    }
#undef LOADGRP
#undef SCANGRP

    __syncthreads();

    // ---- stage C: y[o, t] = sum_p C[p,o] * g[p,t], thread = 8ch x 2t ----
    const int oct = lane & 3;
    const int tl  = wp * 16 + (lane >> 2) * 2;

    u64 a01t0 = 0ull, a23t0 = 0ull, a45t0 = 0ull, a67t0 = 0ull;
    u64 a01t1 = 0ull, a23t1 = 0ull, a45t1 = 0ull, a67t1 = 0ull;

    const float* cb = Cp + oct * 8;
#pragma unroll 8
    for (int pp = 0; pp < NP; ++pp) {
        ulonglong2 cA = *reinterpret_cast<const ulonglong2*>(cb + pp * OUT_CH);
        ulonglong2 cB = *reinterpret_cast<const ulonglong2*>(cb + pp * OUT_CH + 4);
        u64 gp = *reinterpret_cast<const u64*>(&g_s[pp * GST + tl]);
        float g0, g1;
        unpack2(gp, g0, g1);
        u64 gg0 = pack2(g0, g0);
        u64 gg1 = pack2(g1, g1);
        a01t0 = ffma2(cA.x, gg0, a01t0);
        a23t0 = ffma2(cA.y, gg0, a23t0);
        a45t0 = ffma2(cB.x, gg0, a45t0);
        a67t0 = ffma2(cB.y, gg0, a67t0);
        a01t1 = ffma2(cA.x, gg1, a01t1);
        a23t1 = ffma2(cA.y, gg1, a23t1);
        a45t1 = ffma2(cB.x, gg1, a45t1);
        a67t1 = ffma2(cB.y, gg1, a67t1);
    }

    const int tg = t0 + tl;
    float* yb = y + ((size_t)b * OUT_CH + oct * 8) * T_TOT + tg;
    float c0t0, c1t0, c0t1, c1t1;
    unpack2(a01t0, c0t0, c1t0); unpack2(a01t1, c0t1, c1t1);
    *reinterpret_cast<float2*>(yb + 0 * T_TOT) = make_float2(c0t0, c0t1);
    *reinterpret_cast<float2*>(yb + 1 * T_TOT) = make_float2(c1t0, c1t1);
    unpack2(a23t0, c0t0, c1t0); unpack2(a23t1, c0t1, c1t1);
    *reinterpret_cast<float2*>(yb + 2 * T_TOT) = make_float2(c0t0, c0t1);
    *reinterpret_cast<float2*>(yb + 3 * T_TOT) = make_float2(c1t0, c1t1);
    unpack2(a45t0, c0t0, c1t0); unpack2(a45t1, c0t1, c1t1);
    *reinterpret_cast<float2*>(yb + 4 * T_TOT) = make_float2(c0t0, c0t1);
    *reinterpret_cast<float2*>(yb + 5 * T_TOT) = make_float2(c1t0, c1t1);
    unpack2(a67t0, c0t0, c1t0); unpack2(a67t1, c0t1, c1t1);
    *reinterpret_cast<float2*>(yb + 6 * T_TOT) = make_float2(c0t0, c0t1);
    *reinterpret_cast<float2*>(yb + 7 * T_TOT) = make_float2(c1t0, c1t1);
}

extern "C" void kernel_launch(void* const* d_in, const int* in_sizes, int n_in,
                              void* d_out, int out_size)
{
    const float* u   = (const float*)d_in[0];
    const float* rlb = (const float*)d_in[1];
    const float* rom = (const float*)d_in[2];
    const float* Bc  = (const float*)d_in[3];
    const float* Cp  = (const float*)d_in[4];
    float* y = (float*)d_out;

    const int B = in_sizes[0] / (IN_CH * T_TOT);  // 8

    // zero ready-flags each launch (graph-capturable memset node)
    void* flag_ptr = nullptr;
    cudaGetSymbolAddress(&flag_ptr, w_flag);
    cudaMemsetAsync(flag_ptr, 0, sizeof(unsigned int) * MAXB * NCHUNK, 0);

    cudaFuncSetAttribute(ssm_fused_kernel,
                         cudaFuncAttributeMaxDynamicSharedMemorySize, SMEM_BYTES);

    const int nblk = NBLK1 + NCHUNK * B;   // 512 producers + 512 consumers
    ssm_fused_kernel<<<nblk, 128, SMEM_BYTES>>>(u, Bc, rlb, rom, Cp, y);
}